// round 6
// baseline (speedup 1.0000x reference)
#include <cuda_runtime.h>
#include <math.h>

#define Nn 2048
#define Mm 128
#define Hh 128
#define INF 256
#define NTILES 16   // n-tiles in down pass (128 n each)

// ---------------- scratch (device globals; no allocation allowed) ----------
__device__ float g_hs[Nn * Hh];                 // silu(h @ W_pre + b)        [n][w]
__device__ float g_g[3 * Nn * Hh];              // (hs@Wd[l])*gw[n]/norm_l   [l][n][w]
__device__ float g_pair[(size_t)Nn * Mm * 12];  // per pair: x2, sh1(3), sh2(5), pad3
__device__ float g_part[(size_t)NTILES * Mm * Hh * 9]; // partial coarse [nt][m][u][jj]
__device__ float g_cw[Mm * 9 * Hh];             // [m][jj][w]
__device__ float g_outpre[Nn * Hh];             // before W_post

__device__ __forceinline__ float silu_f(float x) { return x / (1.f + __expf(-x)); }

// ---------------- pair table: x2 + real spherical harmonics (lmax=2) -------
__global__ void k_pair(const float* __restrict__ gc, const float* __restrict__ cc) {
    int p = blockIdx.x * 256 + threadIdx.x;
    if (p >= Nn * Mm) return;
    int n = p >> 7, m = p & 127;
    float dx = gc[n * 3 + 0] - cc[m * 3 + 0];
    float dy = gc[n * 3 + 1] - cc[m * 3 + 1];
    float dz = gc[n * 3 + 2] - cc[m * 3 + 2];
    float x2 = dx * dx + dy * dy + dz * dz + 1e-20f;
    float inv = rsqrtf(x2);
    float x = dx * inv, y = dy * inv, z = dz * inv;
    const float s3 = 1.7320508075688772f;
    float4 A = make_float4(x2, x, y, z);
    float4 B = make_float4(s3 * x * z, s3 * x * y,
                           y * y - 0.5f * (x * x + z * z), s3 * y * z);
    float4 C = make_float4(0.5f * s3 * (z * z - x * x), 0.f, 0.f, 0.f);
    float4* o = reinterpret_cast<float4*>(g_pair + (size_t)p * 12);
    o[0] = A; o[1] = B; o[2] = C;
}

// ---------------- hs = silu(h @ W_pre + b_pre) -----------------------------
__global__ void k_pre(const float* __restrict__ h, const float* __restrict__ Wp,
                      const float* __restrict__ bp) {
    __shared__ float sA[16 * INF];
    int n0 = blockIdx.x * 16;
    int tid = threadIdx.x;  // 256 threads
    for (int i = tid; i < 16 * INF; i += 256) sA[i] = h[n0 * INF + i];
    __syncthreads();
    int w = tid & 127, half = tid >> 7;
    float bb = bp[w];
    float acc[8];
#pragma unroll
    for (int j = 0; j < 8; j++) acc[j] = bb;
    for (int u = 0; u < INF; u++) {
        float wv = Wp[u * Hh + w];
#pragma unroll
        for (int j = 0; j < 8; j++) acc[j] += sA[(half * 8 + j) * INF + u] * wv;
    }
#pragma unroll
    for (int j = 0; j < 8; j++)
        g_hs[(n0 + half * 8 + j) * Hh + w] = silu_f(acc[j]);
}

// ---------------- g[l] = (hs @ W_down[l]) * gw[n] / norm_l -----------------
__global__ void k_gdown(const float* __restrict__ Wd, const float* __restrict__ gw) {
    __shared__ float sA[16 * Hh];
    int l = blockIdx.y;
    int n0 = blockIdx.x * 16;
    int tid = threadIdx.x;  // 256
    for (int i = tid; i < 16 * Hh; i += 256) sA[i] = g_hs[n0 * Hh + i];
    __syncthreads();
    int w = tid & 127, half = tid >> 7;
    float acc[8];
#pragma unroll
    for (int j = 0; j < 8; j++) acc[j] = 0.f;
    const float* W = Wd + l * Hh * Hh;
    for (int u = 0; u < Hh; u++) {
        float wv = W[u * Hh + w];
#pragma unroll
        for (int j = 0; j < 8; j++) acc[j] += sA[(half * 8 + j) * Hh + u] * wv;
    }
    float invn = (l == 0) ? 1.f : ((l == 1) ? 0.5773502691896258f : 0.4472135954999579f);
#pragma unroll
    for (int j = 0; j < 8; j++) {
        int n = n0 + half * 8 + j;
        g_g[((size_t)l * Nn + n) * Hh + w] = acc[j] * gw[n] * invn;
    }
}

// ---------------- down pass: partial coarse per n-tile ---------------------
// grid (Mm/4, NTILES), block 128 (thread = w)
__global__ void __launch_bounds__(128) k_down() {
    int w = threadIdx.x;
    int m0 = blockIdx.x * 4;
    int nt = blockIdx.y;
    int n0 = nt * (Nn / NTILES);

    // radial basis constants for channel w
    const float MIN_S = 0.32f * 1.88973f * 0.5f;
    const float MAX_S = 2.32f * 1.88973f * 0.5f;
    float s = MIN_S + (MAX_S - MIN_S) * ((float)w / 127.f);
    float temps = 2.f * s * s;
    float a = 1.f / temps;
    float kcoef = -a * 1.4426950408889634f;          // exp(-a x2) = exp2(kcoef*x2)
    float pt = 3.14159265358979323846f * temps;
    float cradw = (2.f / 3.f) * a / (pt * sqrtf(pt)); // w-only factor, applied at end

    float acc[4][9];
#pragma unroll
    for (int mt = 0; mt < 4; mt++)
#pragma unroll
        for (int jj = 0; jj < 9; jj++) acc[mt][jj] = 0.f;

    const float* g0p = g_g + ((size_t)0 * Nn + n0) * Hh + w;
    const float* g1p = g_g + ((size_t)1 * Nn + n0) * Hh + w;
    const float* g2p = g_g + ((size_t)2 * Nn + n0) * Hh + w;

    for (int i = 0; i < Nn / NTILES; i++) {
        int n = n0 + i;
        float g0 = g0p[i * Hh];
        float g1 = g1p[i * Hh];
        float g2 = g2p[i * Hh];
        const float4* pp = reinterpret_cast<const float4*>(
            g_pair + (size_t)(n * Mm + m0) * 12);
#pragma unroll
        for (int mt = 0; mt < 4; mt++) {
            float4 A = pp[mt * 3 + 0];
            float4 B = pp[mt * 3 + 1];
            float4 C = pp[mt * 3 + 2];
            float x2 = A.x;
            float e = exp2f(kcoef * x2);
            float r = e * x2;
            float t0 = g0 * r, t1 = g1 * r, t2 = g2 * r;
            acc[mt][0] += t0;                 // sh0 == 1
            acc[mt][1] += t1 * A.y;
            acc[mt][2] += t1 * A.z;
            acc[mt][3] += t1 * A.w;
            acc[mt][4] += t2 * B.x;
            acc[mt][5] += t2 * B.y;
            acc[mt][6] += t2 * B.z;
            acc[mt][7] += t2 * B.w;
            acc[mt][8] += t2 * C.x;
        }
    }
#pragma unroll
    for (int mt = 0; mt < 4; mt++)
#pragma unroll
        for (int jj = 0; jj < 9; jj++)
            g_part[(((size_t)nt * Mm + (m0 + mt)) * Hh + w) * 9 + jj] =
                acc[mt][jj] * cradw;
}

// ---------------- cw[m][jj][w] = (1/norm_l) sum_u coarse[m][u][jj] Wup[l][u][w]
// grid Mm, block 128 (thread = w)
__global__ void __launch_bounds__(128) k_cw(const float* __restrict__ Wu) {
    __shared__ float sc[Hh * 9];
    int m = blockIdx.x;
    int w = threadIdx.x;
    for (int i = w; i < Hh * 9; i += 128) {
        float v = 0.f;
#pragma unroll
        for (int nt = 0; nt < NTILES; nt++)
            v += g_part[(size_t)nt * (Mm * Hh * 9) + (size_t)m * (Hh * 9) + i];
        sc[i] = v;
    }
    __syncthreads();
    float acc[9];
#pragma unroll
    for (int jj = 0; jj < 9; jj++) acc[jj] = 0.f;
    for (int u = 0; u < Hh; u++) {
        float w0 = Wu[((0 * Hh + u) * Hh) + w];
        float w1 = Wu[((1 * Hh + u) * Hh) + w];
        float w2 = Wu[((2 * Hh + u) * Hh) + w];
        const float* sv = sc + u * 9;
        acc[0] += sv[0] * w0;
        acc[1] += sv[1] * w1;
        acc[2] += sv[2] * w1;
        acc[3] += sv[3] * w1;
        acc[4] += sv[4] * w2;
        acc[5] += sv[5] * w2;
        acc[6] += sv[6] * w2;
        acc[7] += sv[7] * w2;
        acc[8] += sv[8] * w2;
    }
    const float i1 = 0.5773502691896258f, i2 = 0.4472135954999579f;
    g_cw[(m * 9 + 0) * Hh + w] = acc[0];
    g_cw[(m * 9 + 1) * Hh + w] = acc[1] * i1;
    g_cw[(m * 9 + 2) * Hh + w] = acc[2] * i1;
    g_cw[(m * 9 + 3) * Hh + w] = acc[3] * i1;
    g_cw[(m * 9 + 4) * Hh + w] = acc[4] * i2;
    g_cw[(m * 9 + 5) * Hh + w] = acc[5] * i2;
    g_cw[(m * 9 + 6) * Hh + w] = acc[6] * i2;
    g_cw[(m * 9 + 7) * Hh + w] = acc[7] * i2;
    g_cw[(m * 9 + 8) * Hh + w] = acc[8] * i2;
}

// ---------------- up pass: outpre[n][w] = sum_m sum_jj cw[m][jj][w]*sh[n][m][jj]
// grid Nn/16, block 512 (w = tid&127, quarter = tid>>7 owns 4 n's)
__global__ void __launch_bounds__(512) k_up() {
    int tid = threadIdx.x;
    int w = tid & 127;
    int q = tid >> 7;
    int n0 = blockIdx.x * 16 + q * 4;
    float acc[4] = {0.f, 0.f, 0.f, 0.f};
    for (int m = 0; m < Mm; m++) {
        float cv[9];
#pragma unroll
        for (int jj = 0; jj < 9; jj++) cv[jj] = g_cw[(m * 9 + jj) * Hh + w];
#pragma unroll
        for (int t = 0; t < 4; t++) {
            const float4* pp = reinterpret_cast<const float4*>(
                g_pair + (size_t)((n0 + t) * Mm + m) * 12);
            float4 A = pp[0];
            float4 B = pp[1];
            float4 C = pp[2];
            float v = cv[0];
            v += cv[1] * A.y;
            v += cv[2] * A.z;
            v += cv[3] * A.w;
            v += cv[4] * B.x;
            v += cv[5] * B.y;
            v += cv[6] * B.z;
            v += cv[7] * B.w;
            v += cv[8] * C.x;
            acc[t] += v;
        }
    }
#pragma unroll
    for (int t = 0; t < 4; t++) g_outpre[(n0 + t) * Hh + w] = acc[t];
}

// ---------------- out = silu(outpre @ W_post + b_post) ---------------------
__global__ void k_post(const float* __restrict__ Wp, const float* __restrict__ bp,
                       float* __restrict__ out) {
    __shared__ float sA[16 * Hh];
    int n0 = blockIdx.x * 16;
    int tid = threadIdx.x;  // 256
    for (int i = tid; i < 16 * Hh; i += 256) sA[i] = g_outpre[n0 * Hh + i];
    __syncthreads();
    int w = tid & 127, half = tid >> 7;
    float bb = bp[w];
    float acc[8];
#pragma unroll
    for (int j = 0; j < 8; j++) acc[j] = bb;
    for (int u = 0; u < Hh; u++) {
        float wv = Wp[u * Hh + w];
#pragma unroll
        for (int j = 0; j < 8; j++) acc[j] += sA[(half * 8 + j) * Hh + u] * wv;
    }
#pragma unroll
    for (int j = 0; j < 8; j++)
        out[(n0 + half * 8 + j) * Hh + w] = silu_f(acc[j]);
}

// ---------------- launch ---------------------------------------------------
extern "C" void kernel_launch(void* const* d_in, const int* in_sizes, int n_in,
                              void* d_out, int out_size) {
    const float* h     = (const float*)d_in[0];  // [2048,256]
    const float* gc    = (const float*)d_in[1];  // [2048,3]
    const float* cc    = (const float*)d_in[2];  // [128,3]
    const float* gw    = (const float*)d_in[3];  // [2048]
    const float* Wpre  = (const float*)d_in[4];  // [256,128]
    const float* bpre  = (const float*)d_in[5];  // [128]
    const float* Wd    = (const float*)d_in[6];  // [3,128,128]
    const float* Wu    = (const float*)d_in[7];  // [3,128,128]
    const float* Wpost = (const float*)d_in[8];  // [128,128]
    const float* bpost = (const float*)d_in[9];  // [128]
    float* out = (float*)d_out;                  // [2048,128]

    k_pair<<<(Nn * Mm + 255) / 256, 256>>>(gc, cc);
    k_pre<<<Nn / 16, 256>>>(h, Wpre, bpre);
    k_gdown<<<dim3(Nn / 16, 3), 256>>>(Wd, gw);
    k_down<<<dim3(Mm / 4, NTILES), 128>>>();
    k_cw<<<Mm, 128>>>(Wu);
    k_up<<<Nn / 16, 512>>>();
    k_post<<<Nn / 16, 256>>>(Wpost, bpost, out);
}

// round 7
// speedup vs baseline: 1.0015x; 1.0015x over previous
#include <cuda_runtime.h>
#include <math.h>

#define Nn 2048
#define Mm 128
#define Hh 128
#define INF 256
#define NTILES 16   // n-tiles in down pass (128 n each)

// ---------------- scratch (device globals; no allocation allowed) ----------
__device__ float g_hs[Nn * Hh];                 // silu(h @ W_pre + b)        [n][w]
__device__ float g_g[3 * Nn * Hh];              // (hs@Wd[l])*gw[n]/norm_l   [l][n][w]
__device__ float g_pair[(size_t)Nn * Mm * 12];  // per pair: x2, sh1(3), sh2(5), pad3
__device__ float g_part[(size_t)NTILES * Mm * Hh * 9]; // partial coarse [nt][m][u][jj]
__device__ float g_cw[Mm * 9 * Hh];             // [m][jj][w]
__device__ float g_outpre[Nn * Hh];             // before W_post

__device__ __forceinline__ float silu_f(float x) { return x / (1.f + __expf(-x)); }

// ---------------- pair table: x2 + real spherical harmonics (lmax=2) -------
__global__ void k_pair(const float* __restrict__ gc, const float* __restrict__ cc) {
    int p = blockIdx.x * 256 + threadIdx.x;
    if (p >= Nn * Mm) return;
    int n = p >> 7, m = p & 127;
    float dx = gc[n * 3 + 0] - cc[m * 3 + 0];
    float dy = gc[n * 3 + 1] - cc[m * 3 + 1];
    float dz = gc[n * 3 + 2] - cc[m * 3 + 2];
    float x2 = dx * dx + dy * dy + dz * dz + 1e-20f;
    float inv = rsqrtf(x2);
    float x = dx * inv, y = dy * inv, z = dz * inv;
    const float s3 = 1.7320508075688772f;
    float4 A = make_float4(x2, x, y, z);
    float4 B = make_float4(s3 * x * z, s3 * x * y,
                           y * y - 0.5f * (x * x + z * z), s3 * y * z);
    float4 C = make_float4(0.5f * s3 * (z * z - x * x), 0.f, 0.f, 0.f);
    float4* o = reinterpret_cast<float4*>(g_pair + (size_t)p * 12);
    o[0] = A; o[1] = B; o[2] = C;
}

// ---------------- hs = silu(h @ W_pre + b_pre) -----------------------------
__global__ void k_pre(const float* __restrict__ h, const float* __restrict__ Wp,
                      const float* __restrict__ bp) {
    __shared__ float sA[16 * INF];
    int n0 = blockIdx.x * 16;
    int tid = threadIdx.x;  // 256 threads
    for (int i = tid; i < 16 * INF; i += 256) sA[i] = h[n0 * INF + i];
    __syncthreads();
    int w = tid & 127, half = tid >> 7;
    float bb = bp[w];
    float acc[8];
#pragma unroll
    for (int j = 0; j < 8; j++) acc[j] = bb;
    for (int u = 0; u < INF; u++) {
        float wv = Wp[u * Hh + w];
#pragma unroll
        for (int j = 0; j < 8; j++) acc[j] += sA[(half * 8 + j) * INF + u] * wv;
    }
#pragma unroll
    for (int j = 0; j < 8; j++)
        g_hs[(n0 + half * 8 + j) * Hh + w] = silu_f(acc[j]);
}

// ---------------- g[l] = (hs @ W_down[l]) * gw[n] / norm_l -----------------
__global__ void k_gdown(const float* __restrict__ Wd, const float* __restrict__ gw) {
    __shared__ float sA[16 * Hh];
    int l = blockIdx.y;
    int n0 = blockIdx.x * 16;
    int tid = threadIdx.x;  // 256
    for (int i = tid; i < 16 * Hh; i += 256) sA[i] = g_hs[n0 * Hh + i];
    __syncthreads();
    int w = tid & 127, half = tid >> 7;
    float acc[8];
#pragma unroll
    for (int j = 0; j < 8; j++) acc[j] = 0.f;
    const float* W = Wd + l * Hh * Hh;
    for (int u = 0; u < Hh; u++) {
        float wv = W[u * Hh + w];
#pragma unroll
        for (int j = 0; j < 8; j++) acc[j] += sA[(half * 8 + j) * Hh + u] * wv;
    }
    float invn = (l == 0) ? 1.f : ((l == 1) ? 0.5773502691896258f : 0.4472135954999579f);
#pragma unroll
    for (int j = 0; j < 8; j++) {
        int n = n0 + half * 8 + j;
        g_g[((size_t)l * Nn + n) * Hh + w] = acc[j] * gw[n] * invn;
    }
}

// ---------------- down pass: partial coarse per n-tile ---------------------
// grid (Mm/4, NTILES), block 128 (thread = w)
__global__ void __launch_bounds__(128) k_down() {
    int w = threadIdx.x;
    int m0 = blockIdx.x * 4;
    int nt = blockIdx.y;
    int n0 = nt * (Nn / NTILES);

    // radial basis constants for channel w
    const float MIN_S = 0.32f * 1.88973f * 0.5f;
    const float MAX_S = 2.32f * 1.88973f * 0.5f;
    float s = MIN_S + (MAX_S - MIN_S) * ((float)w / 127.f);
    float temps = 2.f * s * s;
    float a = 1.f / temps;
    float kcoef = -a * 1.4426950408889634f;          // exp(-a x2) = exp2(kcoef*x2)
    float pt = 3.14159265358979323846f * temps;
    float cradw = (2.f / 3.f) * a / (pt * sqrtf(pt)); // w-only factor, applied at end

    float acc[4][9];
#pragma unroll
    for (int mt = 0; mt < 4; mt++)
#pragma unroll
        for (int jj = 0; jj < 9; jj++) acc[mt][jj] = 0.f;

    const float* g0p = g_g + ((size_t)0 * Nn + n0) * Hh + w;
    const float* g1p = g_g + ((size_t)1 * Nn + n0) * Hh + w;
    const float* g2p = g_g + ((size_t)2 * Nn + n0) * Hh + w;

    for (int i = 0; i < Nn / NTILES; i++) {
        int n = n0 + i;
        float g0 = g0p[i * Hh];
        float g1 = g1p[i * Hh];
        float g2 = g2p[i * Hh];
        const float4* pp = reinterpret_cast<const float4*>(
            g_pair + (size_t)(n * Mm + m0) * 12);
#pragma unroll
        for (int mt = 0; mt < 4; mt++) {
            float4 A = pp[mt * 3 + 0];
            float4 B = pp[mt * 3 + 1];
            float4 C = pp[mt * 3 + 2];
            float x2 = A.x;
            float e = exp2f(kcoef * x2);
            float r = e * x2;
            float t0 = g0 * r, t1 = g1 * r, t2 = g2 * r;
            acc[mt][0] += t0;                 // sh0 == 1
            acc[mt][1] += t1 * A.y;
            acc[mt][2] += t1 * A.z;
            acc[mt][3] += t1 * A.w;
            acc[mt][4] += t2 * B.x;
            acc[mt][5] += t2 * B.y;
            acc[mt][6] += t2 * B.z;
            acc[mt][7] += t2 * B.w;
            acc[mt][8] += t2 * C.x;
        }
    }
#pragma unroll
    for (int mt = 0; mt < 4; mt++)
#pragma unroll
        for (int jj = 0; jj < 9; jj++)
            g_part[(((size_t)nt * Mm + (m0 + mt)) * Hh + w) * 9 + jj] =
                acc[mt][jj] * cradw;
}

// ---------------- cw[m][jj][w] = (1/norm_l) sum_u coarse[m][u][jj] Wup[l][u][w]
// grid Mm, block 128 (thread = w)
__global__ void __launch_bounds__(128) k_cw(const float* __restrict__ Wu) {
    __shared__ float sc[Hh * 9];
    int m = blockIdx.x;
    int w = threadIdx.x;
    for (int i = w; i < Hh * 9; i += 128) {
        float v = 0.f;
#pragma unroll
        for (int nt = 0; nt < NTILES; nt++)
            v += g_part[(size_t)nt * (Mm * Hh * 9) + (size_t)m * (Hh * 9) + i];
        sc[i] = v;
    }
    __syncthreads();
    float acc[9];
#pragma unroll
    for (int jj = 0; jj < 9; jj++) acc[jj] = 0.f;
    for (int u = 0; u < Hh; u++) {
        float w0 = Wu[((0 * Hh + u) * Hh) + w];
        float w1 = Wu[((1 * Hh + u) * Hh) + w];
        float w2 = Wu[((2 * Hh + u) * Hh) + w];
        const float* sv = sc + u * 9;
        acc[0] += sv[0] * w0;
        acc[1] += sv[1] * w1;
        acc[2] += sv[2] * w1;
        acc[3] += sv[3] * w1;
        acc[4] += sv[4] * w2;
        acc[5] += sv[5] * w2;
        acc[6] += sv[6] * w2;
        acc[7] += sv[7] * w2;
        acc[8] += sv[8] * w2;
    }
    const float i1 = 0.5773502691896258f, i2 = 0.4472135954999579f;
    g_cw[(m * 9 + 0) * Hh + w] = acc[0];
    g_cw[(m * 9 + 1) * Hh + w] = acc[1] * i1;
    g_cw[(m * 9 + 2) * Hh + w] = acc[2] * i1;
    g_cw[(m * 9 + 3) * Hh + w] = acc[3] * i1;
    g_cw[(m * 9 + 4) * Hh + w] = acc[4] * i2;
    g_cw[(m * 9 + 5) * Hh + w] = acc[5] * i2;
    g_cw[(m * 9 + 6) * Hh + w] = acc[6] * i2;
    g_cw[(m * 9 + 7) * Hh + w] = acc[7] * i2;
    g_cw[(m * 9 + 8) * Hh + w] = acc[8] * i2;
}

// ---------------- up pass: outpre[n][w] = sum_m sum_jj cw[m][jj][w]*sh[n][m][jj]
// grid Nn/16, block 512 (w = tid&127, quarter = tid>>7 owns 4 n's)
__global__ void __launch_bounds__(512) k_up() {
    int tid = threadIdx.x;
    int w = tid & 127;
    int q = tid >> 7;
    int n0 = blockIdx.x * 16 + q * 4;
    float acc[4] = {0.f, 0.f, 0.f, 0.f};
    for (int m = 0; m < Mm; m++) {
        float cv[9];
#pragma unroll
        for (int jj = 0; jj < 9; jj++) cv[jj] = g_cw[(m * 9 + jj) * Hh + w];
#pragma unroll
        for (int t = 0; t < 4; t++) {
            const float4* pp = reinterpret_cast<const float4*>(
                g_pair + (size_t)((n0 + t) * Mm + m) * 12);
            float4 A = pp[0];
            float4 B = pp[1];
            float4 C = pp[2];
            float v = cv[0];
            v += cv[1] * A.y;
            v += cv[2] * A.z;
            v += cv[3] * A.w;
            v += cv[4] * B.x;
            v += cv[5] * B.y;
            v += cv[6] * B.z;
            v += cv[7] * B.w;
            v += cv[8] * C.x;
            acc[t] += v;
        }
    }
#pragma unroll
    for (int t = 0; t < 4; t++) g_outpre[(n0 + t) * Hh + w] = acc[t];
}

// ---------------- out = silu(outpre @ W_post + b_post) ---------------------
__global__ void k_post(const float* __restrict__ Wp, const float* __restrict__ bp,
                       float* __restrict__ out) {
    __shared__ float sA[16 * Hh];
    int n0 = blockIdx.x * 16;
    int tid = threadIdx.x;  // 256
    for (int i = tid; i < 16 * Hh; i += 256) sA[i] = g_outpre[n0 * Hh + i];
    __syncthreads();
    int w = tid & 127, half = tid >> 7;
    float bb = bp[w];
    float acc[8];
#pragma unroll
    for (int j = 0; j < 8; j++) acc[j] = bb;
    for (int u = 0; u < Hh; u++) {
        float wv = Wp[u * Hh + w];
#pragma unroll
        for (int j = 0; j < 8; j++) acc[j] += sA[(half * 8 + j) * Hh + u] * wv;
    }
#pragma unroll
    for (int j = 0; j < 8; j++)
        out[(n0 + half * 8 + j) * Hh + w] = silu_f(acc[j]);
}

// ---------------- launch ---------------------------------------------------
extern "C" void kernel_launch(void* const* d_in, const int* in_sizes, int n_in,
                              void* d_out, int out_size) {
    const float* h     = (const float*)d_in[0];  // [2048,256]
    const float* gc    = (const float*)d_in[1];  // [2048,3]
    const float* cc    = (const float*)d_in[2];  // [128,3]
    const float* gw    = (const float*)d_in[3];  // [2048]
    const float* Wpre  = (const float*)d_in[4];  // [256,128]
    const float* bpre  = (const float*)d_in[5];  // [128]
    const float* Wd    = (const float*)d_in[6];  // [3,128,128]
    const float* Wu    = (const float*)d_in[7];  // [3,128,128]
    const float* Wpost = (const float*)d_in[8];  // [128,128]
    const float* bpost = (const float*)d_in[9];  // [128]
    float* out = (float*)d_out;                  // [2048,128]

    k_pair<<<(Nn * Mm + 255) / 256, 256>>>(gc, cc);
    k_pre<<<Nn / 16, 256>>>(h, Wpre, bpre);
    k_gdown<<<dim3(Nn / 16, 3), 256>>>(Wd, gw);
    k_down<<<dim3(Mm / 4, NTILES), 128>>>();
    k_cw<<<Mm, 128>>>(Wu);
    k_up<<<Nn / 16, 512>>>();
    k_post<<<Nn / 16, 256>>>(Wpost, bpost, out);
}